// round 16
// baseline (speedup 1.0000x reference)
#include <cuda_runtime.h>
#include <cuda_fp16.h>
#include <cstdint>
#include <cstddef>

// Problem constants
#define Bsz 8
#define Hn  16
#define Nn  4096
#define DHn 64
#define Kn  128
#define Dn  1024
#define HD  (Dn / 2)     // u32 (fp16-pair) row stride

// Device scratch (no allocs allowed)
__device__ uint32_t g_kph[Bsz * Kn * HD];          // projected K fp16 pairs
__device__ uint32_t g_vph[Bsz * Kn * HD];          // projected V fp16 pairs
__device__ uint32_t g_PTh[2 * Kn * (Nn / 2)];      // P^T f16 pairs [w][k][n/2]

typedef unsigned long long u64;

// ---------------------------------------------------------------------------
// helpers (fp16)
// ---------------------------------------------------------------------------
__device__ __forceinline__ uint32_t cvt2h(float hi_elem, float lo_elem) {
    uint32_t r;
    asm("cvt.rn.f16x2.f32 %0, %1, %2;" : "=r"(r) : "f"(hi_elem), "f"(lo_elem));
    return r;
}
__device__ __forceinline__ float f16lo(uint32_t p) {
    return __half2float(__ushort_as_half((unsigned short)(p & 0xffffu)));
}
__device__ __forceinline__ float f16hi(uint32_t p) {
    return __half2float(__ushort_as_half((unsigned short)(p >> 16)));
}

#define SWZ128(x) ((x) ^ (((x) >> 3) & 0x70))
#define SWZ256(x) ((x) ^ (((x) >> 4) & 0x70))

#define LDSM4(r, a) \
    asm volatile("ldmatrix.sync.aligned.m8n8.x4.shared.b16 {%0,%1,%2,%3}, [%4];" \
        : "=r"((r)[0]), "=r"((r)[1]), "=r"((r)[2]), "=r"((r)[3]) : "r"(a))
#define LDSM4T(r, a) \
    asm volatile("ldmatrix.sync.aligned.m8n8.x4.trans.shared.b16 {%0,%1,%2,%3}, [%4];" \
        : "=r"((r)[0]), "=r"((r)[1]), "=r"((r)[2]), "=r"((r)[3]) : "r"(a))
#define MMA_F16(c, a, b0v, b1v) \
    asm volatile("mma.sync.aligned.m16n8k16.row.col.f32.f16.f16.f32 " \
        "{%0,%1,%2,%3}, {%4,%5,%6,%7}, {%8,%9}, {%0,%1,%2,%3};" \
        : "+f"((c)[0]), "+f"((c)[1]), "+f"((c)[2]), "+f"((c)[3]) \
        : "r"((a)[0]), "r"((a)[1]), "r"((a)[2]), "r"((a)[3]), "r"(b0v), "r"(b1v))

// 64-thread named barrier for a warp pair (ids 1..4)
#define BAR_PAIR(id) asm volatile("bar.sync %0, 64;" :: "r"(id) : "memory")

__device__ __forceinline__ uint32_t smem_u32(const void* p) {
    uint32_t a;
    asm("{ .reg .u64 t; cvta.to.shared.u64 t, %1; cvt.u32.u64 %0, t; }" : "=r"(a) : "l"(p));
    return a;
}

// split a float4 (scaled) into hi/lo f16x2 pairs (Q only)
__device__ __forceinline__ void split4h(float4 v, float s, uint2& h, uint2& l) {
    v.x *= s; v.y *= s; v.z *= s; v.w *= s;
    uint32_t h01 = cvt2h(v.y, v.x);
    uint32_t h23 = cvt2h(v.w, v.z);
    float h0 = f16lo(h01), h1 = f16hi(h01);
    float h2 = f16lo(h23), h3 = f16hi(h23);
    uint32_t l01 = cvt2h(v.y - h1, v.x - h0);
    uint32_t l23 = cvt2h(v.w - h3, v.z - h2);
    h = make_uint2(h01, h23);
    l = make_uint2(l01, l23);
}

// ============================================================================
// Kernel 0: transpose P [4096 n][128 k] -> f16 PT [w][128 k][4096 n]
// ============================================================================
__global__ void __launch_bounds__(256) ptrans_kernel(
    const float* __restrict__ pk, const float* __restrict__ pv)
{
    __shared__ float sT[128][33];
    const int t  = threadIdx.x;
    const int n0 = blockIdx.x * 32;
    const int w  = blockIdx.y;
    const float* __restrict__ P = w ? pv : pk;

    #pragma unroll
    for (int i = 0; i < 16; i++) {
        int idx = t + 256 * i;
        int r = idx >> 7, c = idx & 127;
        sT[c][r] = P[(size_t)(n0 + r) * Kn + c];
    }
    __syncthreads();

    uint32_t* __restrict__ oh = g_PTh + (size_t)w * Kn * (Nn / 2);
    #pragma unroll
    for (int i = 0; i < 8; i++) {
        int idx = t + 256 * i;
        int k = idx >> 4, pr = idx & 15;
        float x0 = sT[k][2 * pr], x1 = sT[k][2 * pr + 1];
        oh[(size_t)k * (Nn / 2) + (n0 >> 1) + pr] = cvt2h(x1, x0);
    }
}

// ============================================================================
// Kernel 1: fp16 1-pass projection, 128-n chunks (32 chunks, deep window).
//   A smem: 128 k-rows x 256 B (128 n fp16), SWZ256
//   B smem: 128 n-rows x 256 B (128 d fp16), SWZ256
//   Stage 64 KB, double-buffered (128 KB).
//   Accumulation n-order identical to 64-n version => bit-identical results.
// ============================================================================
#define PJ_A 0
#define PJ_B 32768
#define PJ_STAGE 65536
#define PJ_SMEM (2 * PJ_STAGE)

__global__ void __launch_bounds__(512, 1) proj_mma_kernel(
    const float* __restrict__ keys, const float* __restrict__ values)
{
    const int dt = blockIdx.x;
    const int b  = blockIdx.y;
    const int w  = blockIdx.z;

    const float* __restrict__ X = (w ? values : keys) + (size_t)b * Nn * Dn + dt * 128;
    const uint32_t* __restrict__ PTh = g_PTh + (size_t)w * Kn * (Nn / 2);
    uint32_t* __restrict__ Gh = (w ? g_vph : g_kph) + (size_t)b * Kn * HD + dt * 64;

    extern __shared__ __align__(1024) unsigned char dsm[];
    const uint32_t sbase = smem_u32(dsm);

    const int tid  = threadIdx.x;
    const int wid  = tid >> 5, lane = tid & 31;
    const int warp_m = (wid >> 2) * 32;
    const int warp_d = (wid & 3) * 32;

    float acc[2][4][4];
    #pragma unroll
    for (int i = 0; i < 2; i++)
        #pragma unroll
        for (int j = 0; j < 4; j++)
            #pragma unroll
            for (int q = 0; q < 4; q++) acc[i][j][q] = 0.0f;

    uint4  pA[4];    // A: 128 rows x 16 uint4/row = 2048 uint4 / 512 thr = 4
    float4 pB[8];    // X: 128 rows x 32 float4/row = 4096 / 512 = 8

    #pragma unroll
    for (int u = 0; u < 4; u++) {
        int idx = tid + 512 * u;
        int row = idx >> 4, c16 = idx & 15;
        pA[u] = *(const uint4*)&PTh[(size_t)row * (Nn / 2) + c16 * 4];
    }
    #pragma unroll
    for (int u = 0; u < 8; u++) {
        int idx = tid + 512 * u;
        int row = idx >> 5, c4 = idx & 31;
        pB[u] = *(const float4*)&X[(size_t)row * Dn + c4 * 4];
    }

    for (int c = 0; c < 32; ++c) {
        unsigned char* st = dsm + (c & 1) * PJ_STAGE;

        #pragma unroll
        for (int u = 0; u < 4; u++) {
            int idx = tid + 512 * u;
            int row = idx >> 4, c16 = idx & 15;
            uint32_t off = SWZ256((uint32_t)(row * 256 + c16 * 16));
            *(uint4*)(st + PJ_A + off) = pA[u];
        }
        #pragma unroll
        for (int u = 0; u < 8; u++) {
            int idx = tid + 512 * u;
            int row = idx >> 5, c4 = idx & 31;
            float4 v = pB[u];
            uint2 hh;
            hh.x = cvt2h(v.y, v.x);
            hh.y = cvt2h(v.w, v.z);
            uint32_t off = SWZ256((uint32_t)(row * 256 + c4 * 8));
            *(uint2*)(st + PJ_B + off) = hh;
        }
        __syncthreads();

        if (c < 31) {
            int nb = (c + 1) * 128;
            #pragma unroll
            for (int u = 0; u < 4; u++) {
                int idx = tid + 512 * u;
                int row = idx >> 4, c16 = idx & 15;
                pA[u] = *(const uint4*)&PTh[(size_t)row * (Nn / 2) + (nb >> 1) + c16 * 4];
            }
            #pragma unroll
            for (int u = 0; u < 8; u++) {
                int idx = tid + 512 * u;
                int row = idx >> 5, c4 = idx & 31;
                pB[u] = *(const float4*)&X[(size_t)(nb + row) * Dn + c4 * 4];
            }
        }

        const uint32_t sA = sbase + (c & 1) * PJ_STAGE + PJ_A;
        const uint32_t sB = sbase + (c & 1) * PJ_STAGE + PJ_B;
        #pragma unroll
        for (int ks = 0; ks < 8; ks++) {
            uint32_t ah[2][4];
            #pragma unroll
            for (int mi = 0; mi < 2; mi++) {
                uint32_t off = SWZ256((uint32_t)((warp_m + mi * 16 + (lane & 15)) * 256
                                                 + ks * 32 + (lane >> 4) * 16));
                LDSM4(ah[mi], sA + off);
            }
            #pragma unroll
            for (int g2 = 0; g2 < 2; g2++) {
                uint32_t offb = SWZ256((uint32_t)((ks * 16 + (lane & 15)) * 256
                                                  + warp_d * 2 + g2 * 32 + (lane >> 4) * 16));
                uint32_t bh[4];
                LDSM4T(bh, sB + offb);
                #pragma unroll
                for (int mi = 0; mi < 2; mi++) {
                    #pragma unroll
                    for (int jj = 0; jj < 2; jj++) {
                        float* cc = acc[mi][g2 * 2 + jj];
                        MMA_F16(cc, ah[mi], bh[jj * 2], bh[jj * 2 + 1]);
                    }
                }
            }
        }
        __syncthreads();
    }

    // ---- epilogue: fp16 pairs ----
    #pragma unroll
    for (int mi = 0; mi < 2; mi++) {
        #pragma unroll
        for (int j = 0; j < 4; j++) {
            int row = warp_m + mi * 16 + (lane >> 2);
            int cp  = (warp_d + j * 8) / 2 + (lane & 3);   // u32 pair column
            uint32_t h0 = cvt2h(acc[mi][j][1], acc[mi][j][0]);
            uint32_t h1 = cvt2h(acc[mi][j][3], acc[mi][j][2]);
            Gh[(size_t)row * HD + cp]       = h0;
            Gh[(size_t)(row + 8) * HD + cp] = h1;
        }
    }
}

// ============================================================================
// Kernel 2: tensor-core attention (unchanged from round-15 passing version).
// ============================================================================
#define AT_QHI  0
#define AT_QLO  16384
#define AT_KHI  32768
#define AT_VHI  49152
#define AT_SMAX 65536
#define AT_SSUM 66560
#define AT_SMEM 67584

__global__ void __launch_bounds__(256, 2) attn_mma_kernel(
    const float* __restrict__ qg, float* __restrict__ outg)
{
    const int nt = blockIdx.x;
    const int h  = blockIdx.y;
    const int b  = blockIdx.z;

    extern __shared__ __align__(1024) unsigned char smb[];
    const uint32_t sbase = smem_u32(smb);
    float* smax = (float*)(smb + AT_SMAX);
    float* ssum = (float*)(smb + AT_SSUM);

    const int tid  = threadIdx.x;
    const int wid  = tid >> 5, lane = tid & 31;
    const int g    = lane >> 2, tk = lane & 3;
    const int wm   = (wid >> 1) * 32;
    const int kh   = wid & 1;
    const int barid = 1 + (wid >> 1);

    // ---- K/V fill (direct 16B copies) + Q fill+split ----
    {
        const size_t kvb = (size_t)b * Kn * HD + h * 32;
        #pragma unroll
        for (int t = 0; t < 4; t++) {
            int idx = tid + 256 * t;
            int row = idx >> 3, u4 = idx & 7;
            size_t o = kvb + (size_t)row * HD + u4 * 4;
            uint32_t off = SWZ128((uint32_t)(row * 128 + u4 * 16));
            *(uint4*)(smb + AT_KHI + off) = *(const uint4*)&g_kph[o];
            *(uint4*)(smb + AT_VHI + off) = *(const uint4*)&g_vph[o];
        }
        const size_t qbase = ((size_t)b * Nn + (size_t)nt * 128) * Dn + h * 64;
        #pragma unroll
        for (int t = 0; t < 8; t++) {
            int idx = tid + 256 * t;
            int row = idx >> 4, c4 = idx & 15;
            size_t go = (size_t)row * Dn + c4 * 4;
            uint32_t off = SWZ128((uint32_t)(row * 128 + c4 * 8));
            uint2 hh, ll;
            split4h(*(const float4*)&qg[qbase + go], 0.125f, hh, ll);
            *(uint2*)(smb + AT_QHI + off) = hh;
            *(uint2*)(smb + AT_QLO + off) = ll;
        }
    }
    __syncthreads();

    // ---- GEMM1: 2-pass (Q 2-limb x K hi) ----
    float acc[2][8][4];
    #pragma unroll
    for (int i = 0; i < 2; i++)
        #pragma unroll
        for (int j = 0; j < 8; j++)
            #pragma unroll
            for (int q = 0; q < 4; q++) acc[i][j][q] = 0.0f;

    {
        const int wk = kh * 64;
        #pragma unroll
        for (int ks = 0; ks < 4; ks++) {
            uint32_t ah[2][4], al[2][4];
            #pragma unroll
            for (int mi = 0; mi < 2; mi++) {
                uint32_t off = SWZ128((uint32_t)((wm + mi * 16 + (lane & 15)) * 128
                                                 + ks * 32 + (lane >> 4) * 16));
                LDSM4(ah[mi], sbase + AT_QHI + off);
                LDSM4(al[mi], sbase + AT_QLO + off);
            }
            #pragma unroll
            for (int jj = 0; jj < 4; jj++) {
                uint32_t offb = SWZ128((uint32_t)((wk + jj * 16 + (lane & 15)) * 128
                                                  + ks * 32 + (lane >> 4) * 16));
                uint32_t bh[4];
                LDSM4(bh, sbase + AT_KHI + offb);
                #pragma unroll
                for (int mi = 0; mi < 2; mi++) {
                    float* c0 = acc[mi][jj * 2];
                    MMA_F16(c0, ah[mi], bh[0], bh[2]);
                    MMA_F16(c0, al[mi], bh[0], bh[2]);
                    float* c1v = acc[mi][jj * 2 + 1];
                    MMA_F16(c1v, ah[mi], bh[1], bh[3]);
                    MMA_F16(c1v, al[mi], bh[1], bh[3]);
                }
            }
        }
    }

    // ---- softmax part 1: row max (pair-local) ----
    #pragma unroll
    for (int mi = 0; mi < 2; mi++) {
        #pragma unroll
        for (int h2 = 0; h2 < 2; h2++) {
            float m = acc[mi][0][h2 * 2];
            #pragma unroll
            for (int j = 0; j < 8; j++)
                m = fmaxf(m, fmaxf(acc[mi][j][h2 * 2], acc[mi][j][h2 * 2 + 1]));
            m = fmaxf(m, __shfl_xor_sync(0xffffffffu, m, 1));
            m = fmaxf(m, __shfl_xor_sync(0xffffffffu, m, 2));
            if (tk == 0) smax[(wm + mi * 16 + g + h2 * 8) * 2 + kh] = m;
        }
    }
    BAR_PAIR(barid);

    // ---- softmax part 2 ----
    {
        unsigned char* pptr = smb + (kh ? AT_QLO : AT_QHI);
        #pragma unroll
        for (int mi = 0; mi < 2; mi++) {
            #pragma unroll
            for (int h2 = 0; h2 < 2; h2++) {
                int row = wm + mi * 16 + g + h2 * 8;
                float M = fmaxf(smax[row * 2], smax[row * 2 + 1]);
                float s = 0.0f;
                #pragma unroll
                for (int j = 0; j < 8; j++) {
                    float x0 = __expf(acc[mi][j][h2 * 2]     - M);
                    float x1 = __expf(acc[mi][j][h2 * 2 + 1] - M);
                    uint32_t ph = cvt2h(x1, x0);
                    s += f16lo(ph) + f16hi(ph);
                    uint32_t off = SWZ128((uint32_t)(row * 128 + j * 16 + tk * 4));
                    *(uint32_t*)(pptr + off) = ph;
                }
                s += __shfl_xor_sync(0xffffffffu, s, 1);
                s += __shfl_xor_sync(0xffffffffu, s, 2);
                if (tk == 0) ssum[row * 2 + kh] = s;
            }
        }
    }
    BAR_PAIR(barid);

    // ---- GEMM2: 1-pass (P single, V hi) ----
    float o[2][4][4];
    #pragma unroll
    for (int i = 0; i < 2; i++)
        #pragma unroll
        for (int j = 0; j < 4; j++)
            #pragma unroll
            for (int q = 0; q < 4; q++) o[i][j][q] = 0.0f;

    {
        const int wdh = kh * 32;
        #pragma unroll
        for (int ks = 0; ks < 8; ks++) {
            const uint32_t pbase = sbase + (ks < 4 ? AT_QHI : AT_QLO);
            uint32_t ah[2][4];
            #pragma unroll
            for (int mi = 0; mi < 2; mi++) {
                uint32_t off = SWZ128((uint32_t)((wm + mi * 16 + (lane & 15)) * 128
                                                 + (ks & 3) * 32 + (lane >> 4) * 16));
                LDSM4(ah[mi], pbase + off);
            }
            #pragma unroll
            for (int g2 = 0; g2 < 2; g2++) {
                uint32_t offb = SWZ128((uint32_t)((ks * 16 + (lane & 15)) * 128
                                                  + wdh * 2 + g2 * 32 + (lane >> 4) * 16));
                uint32_t bh[4];
                LDSM4T(bh, sbase + AT_VHI + offb);
                #pragma unroll
                for (int mi = 0; mi < 2; mi++) {
                    #pragma unroll
                    for (int jj = 0; jj < 2; jj++) {
                        float* cc = o[mi][g2 * 2 + jj];
                        MMA_F16(cc, ah[mi], bh[jj * 2], bh[jj * 2 + 1]);
                    }
                }
            }
        }
    }

    // ---- epilogue ----
    {
        const int wdh = kh * 32;
        const size_t obase = ((size_t)b * Nn + (size_t)nt * 128) * Dn + h * 64;
        #pragma unroll
        for (int mi = 0; mi < 2; mi++) {
            int r0 = wm + mi * 16 + g;
            int r1 = r0 + 8;
            float ri0 = 1.0f / (ssum[r0 * 2] + ssum[r0 * 2 + 1]);
            float ri1 = 1.0f / (ssum[r1 * 2] + ssum[r1 * 2 + 1]);
            #pragma unroll
            for (int j = 0; j < 4; j++) {
                int col = wdh + j * 8 + tk * 2;
                *(float2*)&outg[obase + (size_t)r0 * Dn + col] =
                    make_float2(o[mi][j][0] * ri0, o[mi][j][1] * ri0);
                *(float2*)&outg[obase + (size_t)r1 * Dn + col] =
                    make_float2(o[mi][j][2] * ri1, o[mi][j][3] * ri1);
            }
        }
    }
}

// ============================================================================
// Launch
// ============================================================================
extern "C" void kernel_launch(void* const* d_in, const int* in_sizes, int n_in,
                              void* d_out, int out_size)
{
    const float* q      = (const float*)d_in[0];
    const float* keys   = (const float*)d_in[1];
    const float* values = (const float*)d_in[2];
    const float* pk     = (const float*)d_in[3];
    const float* pv     = (const float*)d_in[4];
    float* out = (float*)d_out;

    cudaFuncSetAttribute(proj_mma_kernel,
                         cudaFuncAttributeMaxDynamicSharedMemorySize, PJ_SMEM);
    cudaFuncSetAttribute(attn_mma_kernel,
                         cudaFuncAttributeMaxDynamicSharedMemorySize, AT_SMEM);

    ptrans_kernel<<<dim3(Nn / 32, 2), 256>>>(pk, pv);
    proj_mma_kernel<<<dim3(8, Bsz, 2), 512, PJ_SMEM>>>(keys, values);
    attn_mma_kernel<<<dim3(Nn / 128, Hn, Bsz), 256, AT_SMEM>>>(q, out);
}